// round 16
// baseline (speedup 1.0000x reference)
#include <cuda_runtime.h>
#include <cuda_bf16.h>
#include <cuda_pipeline.h>

#define BATCH 128
#define SEQ   256
#define NIN   512
#define NH    1024
#define NOUT  512

typedef __nv_bfloat16 bf16;

// persistent rec: 128 blocks, block owns n-slice of 8 (x4 gates), all m, all K
#define RNB 8
#define RBLOCKS (NH / RNB)       /* 128 */
#define RKC 64
#define RNCH (NH / RKC)          /* 16 */
#define HOFF 1024
#define HSTG 32768
#define NSTG 3
#define WOFF (HOFF + NSTG * HSTG)     /* 99328 */
#define REC_SMEM (WOFF + 131072)      /* 230400 (< 232448 limit) */

// proj v2: 128m x 128n tiles, K-chunk 64, bulk-copy fed
#define PKC 8
#define PSTG 65536
#define PROJ_SMEM (1024 + 2 * PSTG)   /* 132096 */

// fp32 out_gemm tiling
#define TM 64
#define TN 64
#define TK 16
#define SROW 68

// ---------------- scratch (device globals) ----------------
__device__ float g_xproj[(size_t)4 * SEQ * BATCH * NH];
__device__ float g_h[BATCH * NH];
__device__ float g_c[BATCH * NH];
__device__ unsigned g_sync;
// h K-chunked SW128-pre-swizzled: [kc][m 0..127][64] (16KB per kc)
__device__ bf16  g_hA_hi[BATCH * NH];
__device__ bf16  g_hA_lo[BATCH * NH];
__device__ bf16  g_hB_hi[BATCH * NH];
__device__ bf16  g_hB_lo[BATCH * NH];
// Wh per-block layout: [b 0..127][kc 0..15][plane 0..1][32 rows x 128B swz]
__device__ bf16  g_Whr[(size_t)8 * NH * NH];
// x K-chunked SW128-pre-swizzled: [kc 0..7][m 0..32767][64]
__device__ bf16  g_xr_hi[(size_t)BATCH * SEQ * NIN];
__device__ bf16  g_xr_lo[(size_t)BATCH * SEQ * NIN];
// Wx K-chunked SW128-pre-swizzled: [gate][kc 0..7][n 0..1023][64]
__device__ bf16  g_Wxr_hi[(size_t)4 * NH * NIN];
__device__ bf16  g_Wxr_lo[(size_t)4 * NH * NIN];

struct Ptr4 { const float* p[4]; };

__device__ __forceinline__ float fast_sigmoid(float x) { return 1.f / (1.f + __expf(-x)); }
__device__ __forceinline__ float fast_tanh(float x)    { return 2.f * fast_sigmoid(2.f * x) - 1.f; }
__device__ __forceinline__ uint32_t swz128(uint32_t o) { return o ^ ((o >> 3) & 0x70u); }

// ---------------- asm helpers ----------------
__device__ __forceinline__ void mbar_init(uint32_t a, uint32_t cnt)
{
    asm volatile("mbarrier.init.shared.b64 [ %0 ], %1;" :: "r"(a), "r"(cnt) : "memory");
}
__device__ __forceinline__ void mbar_expect_tx(uint32_t a, uint32_t bytes)
{
    asm volatile("mbarrier.arrive.expect_tx.shared.b64 _, [ %0 ], %1;"
                 :: "r"(a), "r"(bytes) : "memory");
}
__device__ __forceinline__ void mbar_wait(uint32_t a, uint32_t parity)
{
    asm volatile(
        "{ .reg .pred P1; "
        "LAB_%=: mbarrier.try_wait.parity.acquire.cta.shared::cta.b64 P1, [ %0 ], %1; "
        "@P1 bra DONE_%=; "
        "bra LAB_%=; "
        "DONE_%=: }"
        :: "r"(a), "r"(parity) : "memory");
}
__device__ __forceinline__ void bulk_copy(uint32_t dst, const void* src, uint32_t bytes,
                                          uint32_t mbar)
{
    asm volatile(
        "cp.async.bulk.shared::cluster.global.mbarrier::complete_tx::bytes "
        "[ %0 ], [ %1 ], %2, [ %3 ];"
        :: "r"(dst), "l"(src), "r"(bytes), "r"(mbar) : "memory");
}
__device__ __forceinline__ void fence_async_shared()
{
    asm volatile("fence.proxy.async.shared::cta;" ::: "memory");
}
__device__ __forceinline__ void ldsm4(uint32_t* r, uint32_t addr)
{
    asm volatile("ldmatrix.sync.aligned.m8n8.x4.shared.b16 { %0, %1, %2, %3 }, [ %4 ];"
                 : "=r"(r[0]), "=r"(r[1]), "=r"(r[2]), "=r"(r[3]) : "r"(addr));
}
__device__ __forceinline__ void mma_bf16(float* c, const uint32_t* a, uint32_t b0, uint32_t b1)
{
    asm volatile(
        "mma.sync.aligned.m16n8k16.row.col.f32.bf16.bf16.f32 "
        "{ %0, %1, %2, %3 }, { %4, %5, %6, %7 }, { %8, %9 }, { %0, %1, %2, %3 };"
        : "+f"(c[0]), "+f"(c[1]), "+f"(c[2]), "+f"(c[3])
        : "r"(a[0]), "r"(a[1]), "r"(a[2]), "r"(a[3]), "r"(b0), "r"(b1));
}

// ---------------- fused setup ----------------
__global__ __launch_bounds__(256) void fused_setup(const float* __restrict__ x,
                                                   Ptr4 Wh, Ptr4 Wx)
{
    const size_t idx = (size_t)blockIdx.x * 256 + threadIdx.x;
    if (idx == 0) { g_sync = 0u; }
    {
        float v = x[idx];
        bf16 hv = __float2bfloat16_rn(v);
        bf16 lv = __float2bfloat16_rn(v - __bfloat162float(hv));
        uint32_t m = (uint32_t)(idx >> 9);
        uint32_t k = (uint32_t)(idx & 511u);
        size_t byte = (size_t)(k >> 6) * 4194304u + swz128(m * 128u + (k & 63u) * 2u);
        *(bf16*)((char*)g_xr_hi + byte) = hv;
        *(bf16*)((char*)g_xr_lo + byte) = lv;
    }
    if (idx < (size_t)4 * NH * NH) {
        int gate = (int)(idx >> 20);
        uint32_t r = (uint32_t)(idx & ((1u << 20) - 1));
        float v = Wh.p[gate][r];
        bf16 hv = __float2bfloat16_rn(v);
        bf16 lv = __float2bfloat16_rn(v - __bfloat162float(hv));
        uint32_t n = r >> 10;
        uint32_t k = r & 1023u;
        uint32_t b = n >> 3;
        uint32_t row32 = (uint32_t)gate * 8u + (n & 7u);
        size_t base = (size_t)b * 131072u + (size_t)(k >> 6) * 8192u;
        uint32_t sw = swz128(row32 * 128u + (k & 63u) * 2u);
        *(bf16*)((char*)g_Whr + base + sw) = hv;
        *(bf16*)((char*)g_Whr + base + 4096u + sw) = lv;
    }
    if (idx < (size_t)4 * NH * NIN) {
        int gate = (int)(idx >> 19);
        uint32_t r = (uint32_t)(idx & ((1u << 19) - 1));
        float v = Wx.p[gate][r];
        bf16 hv = __float2bfloat16_rn(v);
        bf16 lv = __float2bfloat16_rn(v - __bfloat162float(hv));
        uint32_t n = r >> 9;
        uint32_t k = r & 511u;
        size_t byte = (size_t)gate * 1048576u + (size_t)(k >> 6) * 131072u
                    + swz128(n * 128u + (k & 63u) * 2u);
        *(bf16*)((char*)g_Wxr_hi + byte) = hv;
        *(bf16*)((char*)g_Wxr_lo + byte) = lv;
    }
    if (idx < (size_t)BATCH * NH) {
        g_h[idx] = 0.f;
        g_c[idx] = 0.f;
        g_hA_hi[idx] = __float2bfloat16_rn(0.f);
        g_hA_lo[idx] = __float2bfloat16_rn(0.f);
    }
}

// ---------------- persistent weight-stationary recurrence (3-stage h pipe) ----
__global__ __launch_bounds__(256) void rec_persistent()
{
    extern __shared__ __align__(128) unsigned char dynsm[];
    const uint32_t smem_u32 = (uint32_t)__cvta_generic_to_shared(dynsm);

    const int tid  = threadIdx.x;
    const int w    = tid >> 5;
    const int lane = tid & 31;
    const int nbase = blockIdx.x * RNB;

    if (tid == 0) {
        mbar_init(smem_u32 + 0, 1);
        mbar_init(smem_u32 + 8, 1);
        mbar_init(smem_u32 + 16, 1);
        mbar_init(smem_u32 + 24, 1);
        fence_async_shared();
    }
    __syncthreads();

    // one-time weight load
    if (tid == 0) {
        mbar_expect_tx(smem_u32 + 24, 131072u);
        const char* wsrc = (const char*)g_Whr + (size_t)blockIdx.x * 131072u;
        #pragma unroll
        for (int kc = 0; kc < 16; kc++) {
            bulk_copy(smem_u32 + WOFF + kc * 8192, wsrc + (size_t)kc * 8192, 8192u,
                      smem_u32 + 24);
        }
    }
    mbar_wait(smem_u32 + 24, 0u);

    const int frow  = lane & 15;
    const int fhalf = (lane >> 4) << 4;
    const int m0   = w * 16 + (lane >> 2);
    const int en0  = nbase + (lane & 3) * 2;
    const size_t BH = (size_t)BATCH * NH;
    const uint32_t kc_h  = (uint32_t)(en0 >> 6);
    const uint32_t col_h = (uint32_t)(en0 & 63);

    float creg[4];
    #pragma unroll
    for (int q = 0; q < 4; q++) { creg[q] = 0.f; }

    // per-stage phase bits (16 chunks % 3 != 0 -> track explicitly)
    uint32_t ph0 = 0u;
    uint32_t ph1 = 0u;
    uint32_t ph2 = 0u;

    for (int t = 0; t < SEQ; t++) {
        const int par = t & 1;
        const char* hin_hi = (const char*)(par ? g_hB_hi : g_hA_hi);
        const char* hin_lo = (const char*)(par ? g_hB_lo : g_hA_lo);
        bf16* hout_hi = par ? g_hA_hi : g_hB_hi;
        bf16* hout_lo = par ? g_hA_lo : g_hB_lo;

        // xproj prefetch (consumed only at epilogue; latency hidden by mainloop)
        float xp[4][4];
        #pragma unroll
        for (int g = 0; g < 4; g++) {
            #pragma unroll
            for (int half = 0; half < 2; half++) {
                const int em = m0 + half * 8;
                float2 v = *(const float2*)&g_xproj[((size_t)(g * SEQ) + t) * BH
                                                    + (size_t)em * NH + en0];
                xp[g][half * 2]     = v.x;
                xp[g][half * 2 + 1] = v.y;
            }
        }

        // prologue: issue chunks 0 AND 1 back-to-back
        if (tid == 0) {
            fence_async_shared();
            mbar_expect_tx(smem_u32 + 0, 32768u);
            bulk_copy(smem_u32 + HOFF,         hin_hi, 16384u, smem_u32 + 0);
            bulk_copy(smem_u32 + HOFF + 16384, hin_lo, 16384u, smem_u32 + 0);
            mbar_expect_tx(smem_u32 + 8, 32768u);
            bulk_copy(smem_u32 + HOFF + HSTG,         hin_hi + 16384, 16384u, smem_u32 + 8);
            bulk_copy(smem_u32 + HOFF + HSTG + 16384, hin_lo + 16384, 16384u, smem_u32 + 8);
        }

        float acc[4][4];
        #pragma unroll
        for (int g = 0; g < 4; g++) {
            #pragma unroll
            for (int q = 0; q < 4; q++) { acc[g][q] = 0.f; }
        }

        for (int c = 0; c < RNCH; c++) {
            const int st = c % NSTG;
            uint32_t pcur;
            if (st == 0) { pcur = ph0; ph0 ^= 1u; }
            else if (st == 1) { pcur = ph1; ph1 ^= 1u; }
            else { pcur = ph2; ph2 ^= 1u; }
            mbar_wait(smem_u32 + st * 8, pcur);
            __syncthreads();   // all threads done with compute (c-1) -> (c+2) buffer free

            const int cn = c + 2;
            if (cn < RNCH && tid == 0) {
                const int stn = cn % NSTG;
                fence_async_shared();
                mbar_expect_tx(smem_u32 + stn * 8, 32768u);
                bulk_copy(smem_u32 + HOFF + stn * HSTG,
                          hin_hi + (size_t)cn * 16384, 16384u, smem_u32 + stn * 8);
                bulk_copy(smem_u32 + HOFF + stn * HSTG + 16384,
                          hin_lo + (size_t)cn * 16384, 16384u, smem_u32 + stn * 8);
            }

            const uint32_t abase = smem_u32 + HOFF + (uint32_t)(st * HSTG);
            const uint32_t wbase = smem_u32 + WOFF + (uint32_t)(c * 8192);
            #pragma unroll
            for (int ks = 0; ks < 4; ks++) {
                const uint32_t oa  = (uint32_t)((w * 16 + frow) * 128 + ks * 32 + fhalf);
                const uint32_t ob0 = (uint32_t)(frow * 128 + ks * 32 + fhalf);
                const uint32_t ob1 = (uint32_t)((16 + frow) * 128 + ks * 32 + fhalf);
                uint32_t ah[4]; uint32_t al[4];
                uint32_t bh0[4]; uint32_t bh1[4]; uint32_t bl0[4]; uint32_t bl1[4];
                ldsm4(ah, abase + swz128(oa));
                ldsm4(al, abase + 16384u + swz128(oa));
                ldsm4(bh0, wbase + swz128(ob0));
                ldsm4(bh1, wbase + swz128(ob1));
                ldsm4(bl0, wbase + 4096u + swz128(ob0));
                ldsm4(bl1, wbase + 4096u + swz128(ob1));

                mma_bf16(acc[0], ah, bh0[0], bh0[2]);
                mma_bf16(acc[0], ah, bl0[0], bl0[2]);
                mma_bf16(acc[0], al, bh0[0], bh0[2]);

                mma_bf16(acc[1], ah, bh0[1], bh0[3]);
                mma_bf16(acc[1], ah, bl0[1], bl0[3]);
                mma_bf16(acc[1], al, bh0[1], bh0[3]);

                mma_bf16(acc[2], ah, bh1[0], bh1[2]);
                mma_bf16(acc[2], ah, bl1[0], bl1[2]);
                mma_bf16(acc[2], al, bh1[0], bh1[2]);

                mma_bf16(acc[3], ah, bh1[1], bh1[3]);
                mma_bf16(acc[3], ah, bl1[1], bl1[3]);
                mma_bf16(acc[3], al, bh1[1], bh1[3]);
            }
        }

        // epilogue: pure-register cell update
        #pragma unroll
        for (int half = 0; half < 2; half++) {
            const int em = m0 + half * 8;
            float hv[2];
            #pragma unroll
            for (int j = 0; j < 2; j++) {
                const int q = half * 2 + j;
                float fg = fast_sigmoid(acc[0][q] + xp[0][q]);
                float ig = fast_sigmoid(acc[1][q] + xp[1][q]);
                float gg = fast_tanh(acc[2][q] + xp[2][q]);
                float og = fast_sigmoid(acc[3][q] + xp[3][q]);
                float c2 = fg * creg[q] + ig * gg;
                creg[q] = c2;
                hv[j] = og * fast_tanh(c2);
            }
            *(float2*)&g_h[(size_t)em * NH + en0] = make_float2(hv[0], hv[1]);

            __nv_bfloat162 hh = __floats2bfloat162_rn(hv[0], hv[1]);
            float l0 = hv[0] - __bfloat162float(__low2bfloat16(hh));
            float l1 = hv[1] - __bfloat162float(__high2bfloat16(hh));
            const size_t byte = (size_t)kc_h * 16384u
                              + swz128((uint32_t)em * 128u + col_h * 2u);
            *(__nv_bfloat162*)((char*)hout_hi + byte) = hh;
            *(__nv_bfloat162*)((char*)hout_lo + byte) = __floats2bfloat162_rn(l0, l1);
        }

        // grid barrier (all 128 blocks resident)
        if (t < SEQ - 1) {
            __threadfence();
            __syncthreads();
            if (tid == 0) {
                atomicAdd(&g_sync, 1u);
                const unsigned target = (unsigned)(RBLOCKS * (t + 1));
                while (*((volatile unsigned*)&g_sync) < target) { }
            }
            __syncthreads();
        }
    }

    #pragma unroll
    for (int half = 0; half < 2; half++) {
        const int em = m0 + half * 8;
        *(float2*)&g_c[(size_t)em * NH + en0] = make_float2(creg[half * 2], creg[half * 2 + 1]);
    }
}

// ---------------- proj v2: bulk-copy fed 128m x 128n bf16x3 GEMM (unchanged) --
__global__ __launch_bounds__(256) void proj_gemm(Ptr4 Bias)
{
    extern __shared__ __align__(128) unsigned char dynsm[];
    const uint32_t smem_u32 = (uint32_t)__cvta_generic_to_shared(dynsm);

    const int tid  = threadIdx.x;
    const int warp = tid >> 5;
    const int lane = tid & 31;
    const int gate = blockIdx.x >> 3;
    const int nsub = blockIdx.x & 7;
    const int mbase = blockIdx.y * 128;

    if (tid == 0) {
        mbar_init(smem_u32 + 0, 1);
        mbar_init(smem_u32 + 8, 1);
        fence_async_shared();
    }
    __syncthreads();

    const char* srcA0 = (const char*)g_xr_hi + (size_t)mbase * 128;
    const char* srcA1 = (const char*)g_xr_lo + (size_t)mbase * 128;
    const char* srcB0 = (const char*)g_Wxr_hi + (size_t)gate * 1048576u + (size_t)nsub * 16384u;
    const char* srcB1 = (const char*)g_Wxr_lo + (size_t)gate * 1048576u + (size_t)nsub * 16384u;

    if (tid == 0) {
        mbar_expect_tx(smem_u32 + 0, 65536u);
        bulk_copy(smem_u32 + 1024,          srcA0, 16384u, smem_u32 + 0);
        bulk_copy(smem_u32 + 1024 + 16384,  srcA1, 16384u, smem_u32 + 0);
        bulk_copy(smem_u32 + 1024 + 32768,  srcB0, 16384u, smem_u32 + 0);
        bulk_copy(smem_u32 + 1024 + 49152,  srcB1, 16384u, smem_u32 + 0);
    }

    const int wm = warp >> 1;
    const int wn = warp & 1;
    const int frow  = lane & 15;
    const int fhalf = (lane >> 4) << 4;

    float acc[2][8][4];
    #pragma unroll
    for (int mt = 0; mt < 2; mt++) {
        #pragma unroll
        for (int j = 0; j < 8; j++) {
            #pragma unroll
            for (int q = 0; q < 4; q++) { acc[mt][j][q] = 0.f; }
        }
    }

    for (int c = 0; c < PKC; c++) {
        const int st = c & 1;
        mbar_wait(smem_u32 + st * 8, (uint32_t)((c >> 1) & 1));
        __syncthreads();

        const int cn = c + 1;
        if (cn < PKC && tid == 0) {
            const int stn = cn & 1;
            fence_async_shared();
            mbar_expect_tx(smem_u32 + stn * 8, 65536u);
            const uint32_t dst = smem_u32 + 1024 + (uint32_t)(stn * PSTG);
            bulk_copy(dst,          srcA0 + (size_t)cn * 4194304u, 16384u, smem_u32 + stn * 8);
            bulk_copy(dst + 16384,  srcA1 + (size_t)cn * 4194304u, 16384u, smem_u32 + stn * 8);
            bulk_copy(dst + 32768,  srcB0 + (size_t)cn * 131072u, 16384u, smem_u32 + stn * 8);
            bulk_copy(dst + 49152,  srcB1 + (size_t)cn * 131072u, 16384u, smem_u32 + stn * 8);
        }

        const uint32_t su = smem_u32 + 1024 + (uint32_t)(st * PSTG);
        #pragma unroll
        for (int ks = 0; ks < 4; ks++) {
            uint32_t ah[2][4]; uint32_t al[2][4];
            uint32_t bh[4][4]; uint32_t bl[4][4];
            #pragma unroll
            for (int mt = 0; mt < 2; mt++) {
                const uint32_t oa = (uint32_t)((wm * 32 + mt * 16 + frow) * 128
                                               + ks * 32 + fhalf);
                ldsm4(ah[mt], su + swz128(oa));
                ldsm4(al[mt], su + 16384u + swz128(oa));
            }
            #pragma unroll
            for (int bt = 0; bt < 4; bt++) {
                const uint32_t ob = (uint32_t)((wn * 64 + bt * 16 + frow) * 128
                                               + ks * 32 + fhalf);
                ldsm4(bh[bt], su + 32768u + swz128(ob));
                ldsm4(bl[bt], su + 49152u + swz128(ob));
            }
            #pragma unroll
            for (int mt = 0; mt < 2; mt++) {
                #pragma unroll
                for (int bt = 0; bt < 4; bt++) {
                    mma_bf16(acc[mt][bt * 2 + 0], ah[mt], bh[bt][0], bh[bt][2]);
                    mma_bf16(acc[mt][bt * 2 + 0], ah[mt], bl[bt][0], bl[bt][2]);
                    mma_bf16(acc[mt][bt * 2 + 0], al[mt], bh[bt][0], bh[bt][2]);

                    mma_bf16(acc[mt][bt * 2 + 1], ah[mt], bh[bt][1], bh[bt][3]);
                    mma_bf16(acc[mt][bt * 2 + 1], ah[mt], bl[bt][1], bl[bt][3]);
                    mma_bf16(acc[mt][bt * 2 + 1], al[mt], bh[bt][1], bh[bt][3]);
                }
            }
        }
    }

    __syncthreads();
    float* stage = (float*)(dynsm + 1024);
    {
        const int row  = lane >> 2;
        const int colp = (lane & 3) * 2;
        #pragma unroll
        for (int mt = 0; mt < 2; mt++) {
            #pragma unroll
            for (int j = 0; j < 8; j++) {
                const int r0 = wm * 32 + mt * 16 + row;
                const int cc = wn * 64 + j * 8 + colp;
                stage[r0 * 128 + cc]       = acc[mt][j][0];
                stage[r0 * 128 + cc + 1]   = acc[mt][j][1];
                stage[(r0 + 8) * 128 + cc]     = acc[mt][j][2];
                stage[(r0 + 8) * 128 + cc + 1] = acc[mt][j][3];
            }
        }
    }
    __syncthreads();

    const float* __restrict__ bias = Bias.p[gate];
    #pragma unroll
    for (int i = 0; i < 16; i++) {
        const int e   = i * 256 + tid;
        const int row = e >> 5;
        const int c4  = (e & 31) * 4;
        const int m   = mbase + row;
        const int bb  = m >> 8;
        const int ss  = m & 255;
        const int col = nsub * 128 + c4;
        float4 v = *(float4*)(stage + row * 128 + c4);
        v.x += bias[col + 0];
        v.y += bias[col + 1];
        v.z += bias[col + 2];
        v.w += bias[col + 3];
        *(float4*)&g_xproj[(((size_t)gate * SEQ + ss) * BATCH + bb) * NH + col] = v;
    }
}

// ---------------- fp32 output GEMM (small, unchanged) ----------------
__global__ __launch_bounds__(256) void out_gemm(const float* __restrict__ Wy,
                                                const float* __restrict__ by,
                                                float* __restrict__ out)
{
    __shared__ float As[TK][SROW];
    __shared__ float Bs[TK][SROW];
    const int tid = threadIdx.x;
    const int tx = tid & 15;
    const int ty = tid >> 4;
    const int mbase = blockIdx.y * TM;
    const int nbase = blockIdx.x * TN;
    const int lm = tid >> 2;
    const int lk = (tid & 3) << 2;

    float acc[4][4];
    #pragma unroll
    for (int i = 0; i < 4; i++) {
        #pragma unroll
        for (int j = 0; j < 4; j++) { acc[i][j] = 0.f; }
    }

    for (int kt = 0; kt < NH; kt += TK) {
        float4 av = *(const float4*)&g_h[(size_t)(mbase + lm) * NH + kt + lk];
        float4 bv = *(const float4*)&Wy [(size_t)(nbase + lm) * NH + kt + lk];
        __syncthreads();
        As[lk + 0][lm] = av.x; As[lk + 1][lm] = av.y;
        As[lk + 2][lm] = av.z; As[lk + 3][lm] = av.w;
        Bs[lk + 0][lm] = bv.x; Bs[lk + 1][lm] = bv.y;
        Bs[lk + 2][lm] = bv.z; Bs[lk + 3][lm] = bv.w;
        __syncthreads();
        #pragma unroll
        for (int k = 0; k < TK; k++) {
            float ar[4]; float br[4];
            #pragma unroll
            for (int i = 0; i < 4; i++) { ar[i] = As[k][(ty << 2) + i]; }
            #pragma unroll
            for (int j = 0; j < 4; j++) { br[j] = Bs[k][(tx << 2) + j]; }
            #pragma unroll
            for (int i = 0; i < 4; i++) {
                #pragma unroll
                for (int j = 0; j < 4; j++) { acc[i][j] = fmaf(ar[i], br[j], acc[i][j]); }
            }
        }
    }

    #pragma unroll
    for (int i = 0; i < 4; i++) {
        int m = mbase + (ty << 2) + i;
        int n0 = nbase + (tx << 2);
        #pragma unroll
        for (int j = 0; j < 4; j++) {
            out[(size_t)m * NOUT + n0 + j] = acc[i][j] + by[n0 + j];
        }
    }
}

__global__ __launch_bounds__(256) void copy_hc(float* __restrict__ out)
{
    const int idx = blockIdx.x * 256 + threadIdx.x;  // grid 512
    out[(size_t)BATCH * NOUT + idx]                      = g_h[idx];
    out[(size_t)BATCH * NOUT + (size_t)BATCH * NH + idx] = g_c[idx];
}

// ---------------------------------------------------------------------------
extern "C" void kernel_launch(void* const* d_in, const int* in_sizes, int n_in,
                              void* d_out, int out_size)
{
    const float* x_seq = (const float*)d_in[0];
    Ptr4 Wx; Ptr4 Bx; Ptr4 Wh;
    Wx.p[0] = (const float*)d_in[1];  Bx.p[0] = (const float*)d_in[2];  Wh.p[0] = (const float*)d_in[3];
    Wx.p[1] = (const float*)d_in[4];  Bx.p[1] = (const float*)d_in[5];  Wh.p[1] = (const float*)d_in[6];
    Wx.p[2] = (const float*)d_in[7];  Bx.p[2] = (const float*)d_in[8];  Wh.p[2] = (const float*)d_in[9];
    Wx.p[3] = (const float*)d_in[10]; Bx.p[3] = (const float*)d_in[11]; Wh.p[3] = (const float*)d_in[12];
    const float* Why_w = (const float*)d_in[13];
    const float* Why_b = (const float*)d_in[14];
    float* out = (float*)d_out;

    cudaFuncSetAttribute(rec_persistent, cudaFuncAttributeMaxDynamicSharedMemorySize, REC_SMEM);
    cudaFuncSetAttribute(proj_gemm, cudaFuncAttributeMaxDynamicSharedMemorySize, PROJ_SMEM);

    fused_setup<<<65536, 256>>>(x_seq, Wh, Wx);

    proj_gemm<<<dim3(32, 256), 256, PROJ_SMEM>>>(Bx);

    rec_persistent<<<RBLOCKS, 256, REC_SMEM>>>();

    out_gemm<<<dim3(NOUT / TN, BATCH / TM), 256>>>(Why_w, Why_b, out);
    copy_hc<<<512, 256>>>(out);
}

// round 17
// speedup vs baseline: 1.1040x; 1.1040x over previous
#include <cuda_runtime.h>
#include <cuda_bf16.h>
#include <cuda_pipeline.h>

#define BATCH 128
#define SEQ   256
#define NIN   512
#define NH    1024
#define NOUT  512

typedef __nv_bfloat16 bf16;

// persistent rec: 128 blocks, block owns n-slice of 8 (x4 gates), all m, all K
#define RNB 8
#define RBLOCKS (NH / RNB)       /* 128 */
#define RKC 64
#define RNCH (NH / RKC)          /* 16 */
#define HOFF 1024
#define HSTG 32768
#define WOFF (HOFF + 2 * HSTG)        /* 66560 */
#define REC_SMEM (WOFF + 131072)      /* 197632 */

// proj v2: 128m x 128n tiles, K-chunk 64, bulk-copy fed
#define PKC 8
#define PSTG 65536
#define PROJ_SMEM (1024 + 2 * PSTG)   /* 132096 */

// fp32 out_gemm tiling
#define TM 64
#define TN 64
#define TK 16
#define SROW 68

// ---------------- scratch (device globals) ----------------
__device__ float g_xproj[(size_t)4 * SEQ * BATCH * NH];
__device__ float g_h[BATCH * NH];
__device__ float g_c[BATCH * NH];
__device__ unsigned g_sync;
// h K-chunked SW128-pre-swizzled: [kc][m 0..127][64] (16KB per kc)
__device__ bf16  g_hA_hi[BATCH * NH];
__device__ bf16  g_hA_lo[BATCH * NH];
__device__ bf16  g_hB_hi[BATCH * NH];
__device__ bf16  g_hB_lo[BATCH * NH];
// Wh per-block layout: [b 0..127][kc 0..15][plane 0..1][32 rows x 128B swz]
__device__ bf16  g_Whr[(size_t)8 * NH * NH];
// x K-chunked SW128-pre-swizzled: [kc 0..7][m 0..32767][64]
__device__ bf16  g_xr_hi[(size_t)BATCH * SEQ * NIN];
__device__ bf16  g_xr_lo[(size_t)BATCH * SEQ * NIN];
// Wx K-chunked SW128-pre-swizzled: [gate][kc 0..7][n 0..1023][64]
__device__ bf16  g_Wxr_hi[(size_t)4 * NH * NIN];
__device__ bf16  g_Wxr_lo[(size_t)4 * NH * NIN];

struct Ptr4 { const float* p[4]; };

__device__ __forceinline__ float fast_sigmoid(float x) { return 1.f / (1.f + __expf(-x)); }
__device__ __forceinline__ float fast_tanh(float x)    { return 2.f * fast_sigmoid(2.f * x) - 1.f; }
__device__ __forceinline__ uint32_t swz128(uint32_t o) { return o ^ ((o >> 3) & 0x70u); }

// ---------------- asm helpers ----------------
__device__ __forceinline__ void mbar_init(uint32_t a, uint32_t cnt)
{
    asm volatile("mbarrier.init.shared.b64 [ %0 ], %1;" :: "r"(a), "r"(cnt) : "memory");
}
__device__ __forceinline__ void mbar_expect_tx(uint32_t a, uint32_t bytes)
{
    asm volatile("mbarrier.arrive.expect_tx.shared.b64 _, [ %0 ], %1;"
                 :: "r"(a), "r"(bytes) : "memory");
}
__device__ __forceinline__ void mbar_wait(uint32_t a, uint32_t parity)
{
    asm volatile(
        "{ .reg .pred P1; "
        "LAB_%=: mbarrier.try_wait.parity.acquire.cta.shared::cta.b64 P1, [ %0 ], %1; "
        "@P1 bra DONE_%=; "
        "bra LAB_%=; "
        "DONE_%=: }"
        :: "r"(a), "r"(parity) : "memory");
}
__device__ __forceinline__ void bulk_copy(uint32_t dst, const void* src, uint32_t bytes,
                                          uint32_t mbar)
{
    asm volatile(
        "cp.async.bulk.shared::cluster.global.mbarrier::complete_tx::bytes "
        "[ %0 ], [ %1 ], %2, [ %3 ];"
        :: "r"(dst), "l"(src), "r"(bytes), "r"(mbar) : "memory");
}
__device__ __forceinline__ void fence_async_shared()
{
    asm volatile("fence.proxy.async.shared::cta;" ::: "memory");
}
__device__ __forceinline__ void ldsm4(uint32_t* r, uint32_t addr)
{
    asm volatile("ldmatrix.sync.aligned.m8n8.x4.shared.b16 { %0, %1, %2, %3 }, [ %4 ];"
                 : "=r"(r[0]), "=r"(r[1]), "=r"(r[2]), "=r"(r[3]) : "r"(addr));
}
__device__ __forceinline__ void mma_bf16(float* c, const uint32_t* a, uint32_t b0, uint32_t b1)
{
    asm volatile(
        "mma.sync.aligned.m16n8k16.row.col.f32.bf16.bf16.f32 "
        "{ %0, %1, %2, %3 }, { %4, %5, %6, %7 }, { %8, %9 }, { %0, %1, %2, %3 };"
        : "+f"(c[0]), "+f"(c[1]), "+f"(c[2]), "+f"(c[3])
        : "r"(a[0]), "r"(a[1]), "r"(a[2]), "r"(a[3]), "r"(b0), "r"(b1));
}

// ---------------- fused setup ----------------
__global__ __launch_bounds__(256) void fused_setup(const float* __restrict__ x,
                                                   Ptr4 Wh, Ptr4 Wx)
{
    const size_t idx = (size_t)blockIdx.x * 256 + threadIdx.x;
    if (idx == 0) { g_sync = 0u; }
    {
        float v = x[idx];
        bf16 hv = __float2bfloat16_rn(v);
        bf16 lv = __float2bfloat16_rn(v - __bfloat162float(hv));
        uint32_t m = (uint32_t)(idx >> 9);
        uint32_t k = (uint32_t)(idx & 511u);
        size_t byte = (size_t)(k >> 6) * 4194304u + swz128(m * 128u + (k & 63u) * 2u);
        *(bf16*)((char*)g_xr_hi + byte) = hv;
        *(bf16*)((char*)g_xr_lo + byte) = lv;
    }
    if (idx < (size_t)4 * NH * NH) {
        int gate = (int)(idx >> 20);
        uint32_t r = (uint32_t)(idx & ((1u << 20) - 1));
        float v = Wh.p[gate][r];
        bf16 hv = __float2bfloat16_rn(v);
        bf16 lv = __float2bfloat16_rn(v - __bfloat162float(hv));
        uint32_t n = r >> 10;
        uint32_t k = r & 1023u;
        uint32_t b = n >> 3;
        uint32_t row32 = (uint32_t)gate * 8u + (n & 7u);
        size_t base = (size_t)b * 131072u + (size_t)(k >> 6) * 8192u;
        uint32_t sw = swz128(row32 * 128u + (k & 63u) * 2u);
        *(bf16*)((char*)g_Whr + base + sw) = hv;
        *(bf16*)((char*)g_Whr + base + 4096u + sw) = lv;
    }
    if (idx < (size_t)4 * NH * NIN) {
        int gate = (int)(idx >> 19);
        uint32_t r = (uint32_t)(idx & ((1u << 19) - 1));
        float v = Wx.p[gate][r];
        bf16 hv = __float2bfloat16_rn(v);
        bf16 lv = __float2bfloat16_rn(v - __bfloat162float(hv));
        uint32_t n = r >> 9;
        uint32_t k = r & 511u;
        size_t byte = (size_t)gate * 1048576u + (size_t)(k >> 6) * 131072u
                    + swz128(n * 128u + (k & 63u) * 2u);
        *(bf16*)((char*)g_Wxr_hi + byte) = hv;
        *(bf16*)((char*)g_Wxr_lo + byte) = lv;
    }
    if (idx < (size_t)BATCH * NH) {
        g_h[idx] = 0.f;
        g_c[idx] = 0.f;
        g_hA_hi[idx] = __float2bfloat16_rn(0.f);
        g_hA_lo[idx] = __float2bfloat16_rn(0.f);
    }
}

// ---------------- persistent weight-stationary recurrence (512 thr, 16 warps) --
// Warp w: wm = w&7 -> m rows [wm*16, wm*16+16); wg = w>>3 -> gates {2wg, 2wg+1}.
// 2-stage h pipeline identical to R15. Epilogue stages accs in smem (gate-pair
// split means a thread doesn't own all 4 gates), then 2 cells/thread in regs.
__global__ __launch_bounds__(512) void rec_persistent()
{
    extern __shared__ __align__(128) unsigned char dynsm[];
    const uint32_t smem_u32 = (uint32_t)__cvta_generic_to_shared(dynsm);

    const int tid  = threadIdx.x;
    const int w    = tid >> 5;
    const int lane = tid & 31;
    const int nbase = blockIdx.x * RNB;

    if (tid == 0) {
        mbar_init(smem_u32 + 0, 1);
        mbar_init(smem_u32 + 8, 1);
        mbar_init(smem_u32 + 16, 1);
        fence_async_shared();
    }
    __syncthreads();

    // one-time weight load
    if (tid == 0) {
        mbar_expect_tx(smem_u32 + 16, 131072u);
        const char* wsrc = (const char*)g_Whr + (size_t)blockIdx.x * 131072u;
        #pragma unroll
        for (int kc = 0; kc < 16; kc++) {
            bulk_copy(smem_u32 + WOFF + kc * 8192, wsrc + (size_t)kc * 8192, 8192u,
                      smem_u32 + 16);
        }
    }
    mbar_wait(smem_u32 + 16, 0u);

    const int wm = w & 7;      // m-sixteenth
    const int wg = w >> 3;     // gate pair 0..1
    const int frow  = lane & 15;
    const int fhalf = (lane >> 4) << 4;

    // epilogue cell ownership: 2 cells per thread
    const int em  = tid >> 2;            // m 0..127
    const int en0 = nbase + (tid & 3) * 2;
    const size_t BH = (size_t)BATCH * NH;
    const uint32_t kc_h  = (uint32_t)(en0 >> 6);
    const uint32_t col_h = (uint32_t)(en0 & 63);

    float creg[2];
    creg[0] = 0.f;
    creg[1] = 0.f;

    for (int t = 0; t < SEQ; t++) {
        const int par = t & 1;
        const char* hin_hi = (const char*)(par ? g_hB_hi : g_hA_hi);
        const char* hin_lo = (const char*)(par ? g_hB_lo : g_hA_lo);
        bf16* hout_hi = par ? g_hA_hi : g_hB_hi;
        bf16* hout_lo = par ? g_hA_lo : g_hB_lo;

        // xproj prefetch for this thread's 2 cells x 4 gates
        float xp[4][2];
        #pragma unroll
        for (int g = 0; g < 4; g++) {
            float2 v = *(const float2*)&g_xproj[((size_t)(g * SEQ) + t) * BH
                                                + (size_t)em * NH + en0];
            xp[g][0] = v.x;
            xp[g][1] = v.y;
        }

        // prologue: chunk 0 into stage 0
        if (tid == 0) {
            fence_async_shared();
            mbar_expect_tx(smem_u32 + 0, 32768u);
            bulk_copy(smem_u32 + HOFF,         hin_hi, 16384u, smem_u32 + 0);
            bulk_copy(smem_u32 + HOFF + 16384, hin_lo, 16384u, smem_u32 + 0);
        }

        float acc[2][4];
        #pragma unroll
        for (int g = 0; g < 2; g++) {
            #pragma unroll
            for (int q = 0; q < 4; q++) { acc[g][q] = 0.f; }
        }

        for (int c = 0; c < RNCH; c++) {
            const int st = c & 1;
            const uint32_t parity = (uint32_t)((t * 8 + (c >> 1)) & 1);
            mbar_wait(smem_u32 + st * 8, parity);
            __syncthreads();

            const int cn = c + 1;
            if (cn < RNCH && tid == 0) {
                const int stn = cn & 1;
                fence_async_shared();
                mbar_expect_tx(smem_u32 + stn * 8, 32768u);
                bulk_copy(smem_u32 + HOFF + stn * HSTG,
                          hin_hi + (size_t)cn * 16384, 16384u, smem_u32 + stn * 8);
                bulk_copy(smem_u32 + HOFF + stn * HSTG + 16384,
                          hin_lo + (size_t)cn * 16384, 16384u, smem_u32 + stn * 8);
            }

            const uint32_t abase = smem_u32 + HOFF + (uint32_t)(st * HSTG);
            const uint32_t wbase = smem_u32 + WOFF + (uint32_t)(c * 8192);
            #pragma unroll
            for (int ks = 0; ks < 4; ks++) {
                const uint32_t oa = (uint32_t)((wm * 16 + frow) * 128 + ks * 32 + fhalf);
                const uint32_t ob = (uint32_t)((wg * 16 + frow) * 128 + ks * 32 + fhalf);
                uint32_t ah[4]; uint32_t al[4]; uint32_t bh[4]; uint32_t bl[4];
                ldsm4(ah, abase + swz128(oa));
                ldsm4(al, abase + 16384u + swz128(oa));
                ldsm4(bh, wbase + swz128(ob));
                ldsm4(bl, wbase + 4096u + swz128(ob));

                mma_bf16(acc[0], ah, bh[0], bh[2]);
                mma_bf16(acc[0], ah, bl[0], bl[2]);
                mma_bf16(acc[0], al, bh[0], bh[2]);

                mma_bf16(acc[1], ah, bh[1], bh[3]);
                mma_bf16(acc[1], ah, bl[1], bl[3]);
                mma_bf16(acc[1], al, bh[1], bh[3]);
            }
        }

        // stage accs in smem: stage[gate][m 0..127][n 0..7] (16 KB over stage-0 buf)
        __syncthreads();   // everyone done reading h stages
        float* stage = (float*)(dynsm + HOFF);
        {
            const int row  = lane >> 2;
            const int colp = (lane & 3) * 2;
            #pragma unroll
            for (int g = 0; g < 2; g++) {
                const int gate = wg * 2 + g;
                float* b0 = stage + ((gate * 128) + wm * 16 + row) * RNB;
                float* b8 = stage + ((gate * 128) + wm * 16 + row + 8) * RNB;
                b0[colp]     = acc[g][0];
                b0[colp + 1] = acc[g][1];
                b8[colp]     = acc[g][2];
                b8[colp + 1] = acc[g][3];
            }
        }
        __syncthreads();

        // cell update: 2 cells per thread, pure register math after smem reads
        {
            float pf[2]; float pi2[2]; float pg2[2]; float po2[2];
            float2 v;
            v = *(float2*)(stage + ((0 * 128) + em) * RNB + (tid & 3) * 2);
            pf[0] = v.x; pf[1] = v.y;
            v = *(float2*)(stage + ((1 * 128) + em) * RNB + (tid & 3) * 2);
            pi2[0] = v.x; pi2[1] = v.y;
            v = *(float2*)(stage + ((2 * 128) + em) * RNB + (tid & 3) * 2);
            pg2[0] = v.x; pg2[1] = v.y;
            v = *(float2*)(stage + ((3 * 128) + em) * RNB + (tid & 3) * 2);
            po2[0] = v.x; po2[1] = v.y;

            float hv[2];
            #pragma unroll
            for (int j = 0; j < 2; j++) {
                float fg = fast_sigmoid(pf[j] + xp[0][j]);
                float ig = fast_sigmoid(pi2[j] + xp[1][j]);
                float gg = fast_tanh(pg2[j] + xp[2][j]);
                float og = fast_sigmoid(po2[j] + xp[3][j]);
                float c2 = fg * creg[j] + ig * gg;
                creg[j] = c2;
                hv[j] = og * fast_tanh(c2);
            }

            if (t == SEQ - 1) {
                *(float2*)&g_h[(size_t)em * NH + en0] = make_float2(hv[0], hv[1]);
            }

            __nv_bfloat162 hh = __floats2bfloat162_rn(hv[0], hv[1]);
            float l0 = hv[0] - __bfloat162float(__low2bfloat16(hh));
            float l1 = hv[1] - __bfloat162float(__high2bfloat16(hh));
            const size_t byte = (size_t)kc_h * 16384u
                              + swz128((uint32_t)em * 128u + col_h * 2u);
            *(__nv_bfloat162*)((char*)hout_hi + byte) = hh;
            *(__nv_bfloat162*)((char*)hout_lo + byte) = __floats2bfloat162_rn(l0, l1);
        }

        // grid barrier (all 128 blocks resident)
        if (t < SEQ - 1) {
            __threadfence();
            __syncthreads();
            if (tid == 0) {
                atomicAdd(&g_sync, 1u);
                const unsigned target = (unsigned)(RBLOCKS * (t + 1));
                while (*((volatile unsigned*)&g_sync) < target) { }
            }
            __syncthreads();
        }
    }

    *(float2*)&g_c[(size_t)em * NH + en0] = make_float2(creg[0], creg[1]);
}

// ---------------- proj v2: bulk-copy fed 128m x 128n bf16x3 GEMM (unchanged) --
__global__ __launch_bounds__(256) void proj_gemm(Ptr4 Bias)
{
    extern __shared__ __align__(128) unsigned char dynsm[];
    const uint32_t smem_u32 = (uint32_t)__cvta_generic_to_shared(dynsm);

    const int tid  = threadIdx.x;
    const int warp = tid >> 5;
    const int lane = tid & 31;
    const int gate = blockIdx.x >> 3;
    const int nsub = blockIdx.x & 7;
    const int mbase = blockIdx.y * 128;

    if (tid == 0) {
        mbar_init(smem_u32 + 0, 1);
        mbar_init(smem_u32 + 8, 1);
        fence_async_shared();
    }
    __syncthreads();

    const char* srcA0 = (const char*)g_xr_hi + (size_t)mbase * 128;
    const char* srcA1 = (const char*)g_xr_lo + (size_t)mbase * 128;
    const char* srcB0 = (const char*)g_Wxr_hi + (size_t)gate * 1048576u + (size_t)nsub * 16384u;
    const char* srcB1 = (const char*)g_Wxr_lo + (size_t)gate * 1048576u + (size_t)nsub * 16384u;

    if (tid == 0) {
        mbar_expect_tx(smem_u32 + 0, 65536u);
        bulk_copy(smem_u32 + 1024,          srcA0, 16384u, smem_u32 + 0);
        bulk_copy(smem_u32 + 1024 + 16384,  srcA1, 16384u, smem_u32 + 0);
        bulk_copy(smem_u32 + 1024 + 32768,  srcB0, 16384u, smem_u32 + 0);
        bulk_copy(smem_u32 + 1024 + 49152,  srcB1, 16384u, smem_u32 + 0);
    }

    const int wm = warp >> 1;
    const int wn = warp & 1;
    const int frow  = lane & 15;
    const int fhalf = (lane >> 4) << 4;

    float acc[2][8][4];
    #pragma unroll
    for (int mt = 0; mt < 2; mt++) {
        #pragma unroll
        for (int j = 0; j < 8; j++) {
            #pragma unroll
            for (int q = 0; q < 4; q++) { acc[mt][j][q] = 0.f; }
        }
    }

    for (int c = 0; c < PKC; c++) {
        const int st = c & 1;
        mbar_wait(smem_u32 + st * 8, (uint32_t)((c >> 1) & 1));
        __syncthreads();

        const int cn = c + 1;
        if (cn < PKC && tid == 0) {
            const int stn = cn & 1;
            fence_async_shared();
            mbar_expect_tx(smem_u32 + stn * 8, 65536u);
            const uint32_t dst = smem_u32 + 1024 + (uint32_t)(stn * PSTG);
            bulk_copy(dst,          srcA0 + (size_t)cn * 4194304u, 16384u, smem_u32 + stn * 8);
            bulk_copy(dst + 16384,  srcA1 + (size_t)cn * 4194304u, 16384u, smem_u32 + stn * 8);
            bulk_copy(dst + 32768,  srcB0 + (size_t)cn * 131072u, 16384u, smem_u32 + stn * 8);
            bulk_copy(dst + 49152,  srcB1 + (size_t)cn * 131072u, 16384u, smem_u32 + stn * 8);
        }

        const uint32_t su = smem_u32 + 1024 + (uint32_t)(st * PSTG);
        #pragma unroll
        for (int ks = 0; ks < 4; ks++) {
            uint32_t ah[2][4]; uint32_t al[2][4];
            uint32_t bh[4][4]; uint32_t bl[4][4];
            #pragma unroll
            for (int mt = 0; mt < 2; mt++) {
                const uint32_t oa = (uint32_t)((wm * 32 + mt * 16 + frow) * 128
                                               + ks * 32 + fhalf);
                ldsm4(ah[mt], su + swz128(oa));
                ldsm4(al[mt], su + 16384u + swz128(oa));
            }
            #pragma unroll
            for (int bt = 0; bt < 4; bt++) {
                const uint32_t ob = (uint32_t)((wn * 64 + bt * 16 + frow) * 128
                                               + ks * 32 + fhalf);
                ldsm4(bh[bt], su + 32768u + swz128(ob));
                ldsm4(bl[bt], su + 49152u + swz128(ob));
            }
            #pragma unroll
            for (int mt = 0; mt < 2; mt++) {
                #pragma unroll
                for (int bt = 0; bt < 4; bt++) {
                    mma_bf16(acc[mt][bt * 2 + 0], ah[mt], bh[bt][0], bh[bt][2]);
                    mma_bf16(acc[mt][bt * 2 + 0], ah[mt], bl[bt][0], bl[bt][2]);
                    mma_bf16(acc[mt][bt * 2 + 0], al[mt], bh[bt][0], bh[bt][2]);

                    mma_bf16(acc[mt][bt * 2 + 1], ah[mt], bh[bt][1], bh[bt][3]);
                    mma_bf16(acc[mt][bt * 2 + 1], ah[mt], bl[bt][1], bl[bt][3]);
                    mma_bf16(acc[mt][bt * 2 + 1], al[mt], bh[bt][1], bh[bt][3]);
                }
            }
        }
    }

    __syncthreads();
    float* stage = (float*)(dynsm + 1024);
    {
        const int row  = lane >> 2;
        const int colp = (lane & 3) * 2;
        #pragma unroll
        for (int mt = 0; mt < 2; mt++) {
            #pragma unroll
            for (int j = 0; j < 8; j++) {
                const int r0 = wm * 32 + mt * 16 + row;
                const int cc = wn * 64 + j * 8 + colp;
                stage[r0 * 128 + cc]       = acc[mt][j][0];
                stage[r0 * 128 + cc + 1]   = acc[mt][j][1];
                stage[(r0 + 8) * 128 + cc]     = acc[mt][j][2];
                stage[(r0 + 8) * 128 + cc + 1] = acc[mt][j][3];
            }
        }
    }
    __syncthreads();

    const float* __restrict__ bias = Bias.p[gate];
    #pragma unroll
    for (int i = 0; i < 16; i++) {
        const int e   = i * 256 + tid;
        const int row = e >> 5;
        const int c4  = (e & 31) * 4;
        const int m   = mbase + row;
        const int bb  = m >> 8;
        const int ss  = m & 255;
        const int col = nsub * 128 + c4;
        float4 v = *(float4*)(stage + row * 128 + c4);
        v.x += bias[col + 0];
        v.y += bias[col + 1];
        v.z += bias[col + 2];
        v.w += bias[col + 3];
        *(float4*)&g_xproj[(((size_t)gate * SEQ + ss) * BATCH + bb) * NH + col] = v;
    }
}

// ---------------- fp32 output GEMM (small, unchanged) ----------------
__global__ __launch_bounds__(256) void out_gemm(const float* __restrict__ Wy,
                                                const float* __restrict__ by,
                                                float* __restrict__ out)
{
    __shared__ float As[TK][SROW];
    __shared__ float Bs[TK][SROW];
    const int tid = threadIdx.x;
    const int tx = tid & 15;
    const int ty = tid >> 4;
    const int mbase = blockIdx.y * TM;
    const int nbase = blockIdx.x * TN;
    const int lm = tid >> 2;
    const int lk = (tid & 3) << 2;

    float acc[4][4];
    #pragma unroll
    for (int i = 0; i < 4; i++) {
        #pragma unroll
        for (int j = 0; j < 4; j++) { acc[i][j] = 0.f; }
    }

    for (int kt = 0; kt < NH; kt += TK) {
        float4 av = *(const float4*)&g_h[(size_t)(mbase + lm) * NH + kt + lk];
        float4 bv = *(const float4*)&Wy [(size_t)(nbase + lm) * NH + kt + lk];
        __syncthreads();
        As[lk + 0][lm] = av.x; As[lk + 1][lm] = av.y;
        As[lk + 2][lm] = av.z; As[lk + 3][lm] = av.w;
        Bs[lk + 0][lm] = bv.x; Bs[lk + 1][lm] = bv.y;
        Bs[lk + 2][lm] = bv.z; Bs[lk + 3][lm] = bv.w;
        __syncthreads();
        #pragma unroll
        for (int k = 0; k < TK; k++) {
            float ar[4]; float br[4];
            #pragma unroll
            for (int i = 0; i < 4; i++) { ar[i] = As[k][(ty << 2) + i]; }
            #pragma unroll
            for (int j = 0; j < 4; j++) { br[j] = Bs[k][(tx << 2) + j]; }
            #pragma unroll
            for (int i = 0; i < 4; i++) {
                #pragma unroll
                for (int j = 0; j < 4; j++) { acc[i][j] = fmaf(ar[i], br[j], acc[i][j]); }
            }
        }
    }

    #pragma unroll
    for (int i = 0; i < 4; i++) {
        int m = mbase + (ty << 2) + i;
        int n0 = nbase + (tx << 2);
        #pragma unroll
        for (int j = 0; j < 4; j++) {
            out[(size_t)m * NOUT + n0 + j] = acc[i][j] + by[n0 + j];
        }
    }
}

__global__ __launch_bounds__(256) void copy_hc(float* __restrict__ out)
{
    const int idx = blockIdx.x * 256 + threadIdx.x;  // grid 512
    out[(size_t)BATCH * NOUT + idx]                      = g_h[idx];
    out[(size_t)BATCH * NOUT + (size_t)BATCH * NH + idx] = g_c[idx];
}

// ---------------------------------------------------------------------------
extern "C" void kernel_launch(void* const* d_in, const int* in_sizes, int n_in,
                              void* d_out, int out_size)
{
    const float* x_seq = (const float*)d_in[0];
    Ptr4 Wx; Ptr4 Bx; Ptr4 Wh;
    Wx.p[0] = (const float*)d_in[1];  Bx.p[0] = (const float*)d_in[2];  Wh.p[0] = (const float*)d_in[3];
    Wx.p[1] = (const float*)d_in[4];  Bx.p[1] = (const float*)d_in[5];  Wh.p[1] = (const float*)d_in[6];
    Wx.p[2] = (const float*)d_in[7];  Bx.p[2] = (const float*)d_in[8];  Wh.p[2] = (const float*)d_in[9];
    Wx.p[3] = (const float*)d_in[10]; Bx.p[3] = (const float*)d_in[11]; Wh.p[3] = (const float*)d_in[12];
    const float* Why_w = (const float*)d_in[13];
    const float* Why_b = (const float*)d_in[14];
    float* out = (float*)d_out;

    cudaFuncSetAttribute(rec_persistent, cudaFuncAttributeMaxDynamicSharedMemorySize, REC_SMEM);
    cudaFuncSetAttribute(proj_gemm, cudaFuncAttributeMaxDynamicSharedMemorySize, PROJ_SMEM);

    fused_setup<<<65536, 256>>>(x_seq, Wh, Wx);

    proj_gemm<<<dim3(32, 256), 256, PROJ_SMEM>>>(Bx);

    rec_persistent<<<RBLOCKS, 512, REC_SMEM>>>();

    out_gemm<<<dim3(NOUT / TN, BATCH / TM), 256>>>(Why_w, Why_b, out);
    copy_hc<<<512, 256>>>(out);
}